// round 9
// baseline (speedup 1.0000x reference)
#include <cuda_runtime.h>
#include <cuda_bf16.h>
#include <cstdint>

#define B_   4
#define N_   1024
#define DM_  1024
#define H_   16
#define DK_  64
#define DV_  1024

// ---------------- scratch (device globals) ----------------
__device__ __nv_bfloat16 g_qh [B_ * N_ * DM_],  g_ql [B_ * N_ * DM_];
__device__ __nv_bfloat16 g_kh [B_ * N_ * DM_],  g_kl [B_ * N_ * DM_];
__device__ __nv_bfloat16 g_wqTh[H_ * DK_ * DM_], g_wqTl[H_ * DK_ * DM_];
__device__ __nv_bfloat16 g_wkTh[H_ * DK_ * DM_], g_wkTl[H_ * DK_ * DM_];
__device__ __nv_bfloat16 g_Qh [B_ * H_ * N_ * DK_], g_Ql [B_ * H_ * N_ * DK_];
__device__ __nv_bfloat16 g_Kh [B_ * H_ * N_ * DK_], g_Kl [B_ * H_ * N_ * DK_];
__device__ float         g_Sf [B_ * H_ * N_ * N_];
__device__ __nv_bfloat16 g_Sh [B_ * H_ * N_ * N_],  g_Sl [B_ * H_ * N_ * N_];
__device__ __nv_bfloat16 g_Vth[B_ * H_ * DV_ * N_], g_Vtl[B_ * H_ * DV_ * N_];
__device__ float         g_Of [B_ * H_ * N_ * DV_];
// int8 limb planes + scales
__device__ int8_t g_v1 [B_ * N_ * DM_],   g_v0 [B_ * N_ * DM_];
__device__ float  g_sv [B_ * N_];
__device__ int8_t g_wv1[H_ * DV_ * DM_],  g_wv0[H_ * DV_ * DM_];
__device__ float  g_swv[H_ * DV_];
__device__ int8_t g_wo1[DM_ * H_ * DV_],  g_wo0[DM_ * H_ * DV_];
__device__ float  g_swo[DM_];
__device__ int8_t g_P1 [B_ * DV_ * H_ * N_], g_P0 [B_ * DV_ * H_ * N_];
__device__ float  g_sp [B_ * DV_];

// ---------------- helpers ----------------
__device__ __forceinline__ uint32_t smem_u32(const void* p) {
    uint32_t a;
    asm("{ .reg .u64 t; cvta.to.shared.u64 t, %1; cvt.u32.u64 %0, t; }" : "=r"(a) : "l"(p));
    return a;
}
__device__ __forceinline__ void split_bf16(float x, __nv_bfloat16& h, __nv_bfloat16& l) {
    h = __float2bfloat16_rn(x);
    l = __float2bfloat16_rn(x - __bfloat162float(h));
}
__device__ __forceinline__ void cp_async16(uint32_t saddr, const void* gptr) {
    asm volatile("cp.async.cg.shared.global [%0], [%1], 16;" :: "r"(saddr), "l"(gptr));
}
__device__ __forceinline__ uint32_t lds_u32(const __nv_bfloat16* p) {
    return *reinterpret_cast<const uint32_t*>(p);
}
__device__ __forceinline__ void mma_bf16(float* c,
    uint32_t a0, uint32_t a1, uint32_t a2, uint32_t a3, uint32_t b0, uint32_t b1) {
    asm volatile(
        "mma.sync.aligned.m16n8k16.row.col.f32.bf16.bf16.f32 "
        "{%0,%1,%2,%3}, {%4,%5,%6,%7}, {%8,%9}, {%0,%1,%2,%3};"
        : "+f"(c[0]), "+f"(c[1]), "+f"(c[2]), "+f"(c[3])
        : "r"(a0), "r"(a1), "r"(a2), "r"(a3), "r"(b0), "r"(b1));
}
__device__ __forceinline__ void mma_s8(int* c,
    uint32_t a0, uint32_t a1, uint32_t a2, uint32_t a3, uint32_t b0, uint32_t b1) {
    asm volatile(
        "mma.sync.aligned.m16n8k32.row.col.s32.s8.s8.s32 "
        "{%0,%1,%2,%3}, {%4,%5,%6,%7}, {%8,%9}, {%0,%1,%2,%3};"
        : "+r"(c[0]), "+r"(c[1]), "+r"(c[2]), "+r"(c[3])
        : "r"(a0), "r"(a1), "r"(a2), "r"(a3), "r"(b0), "r"(b1));
}
#define LDSM4(r, addr) \
    asm volatile("ldmatrix.sync.aligned.m8n8.x4.shared.b16 {%0,%1,%2,%3}, [%4];" \
        : "=r"((r)[0]), "=r"((r)[1]), "=r"((r)[2]), "=r"((r)[3]) : "r"(addr))

// x ~= (128*q1 + q0) * s exactly over the 14.x-bit grid, |t|<=16256
__device__ __forceinline__ void quant2(float x, float inv, int8_t& q1, int8_t& q0) {
    float t = rintf(x * inv);
    int i1 = __float2int_rn(t * (1.0f / 128.0f));
    int i0 = __float2int_rn(t) - (i1 << 7);
    q1 = (int8_t)i1; q0 = (int8_t)i0;
}

// ===========================================================================
// INT8 2-limb GEMM: C[m,n] = sum_k A[m,k]*B[n,k],  A=(128a1+a0)sA[m], B likewise.
// 3 IMMA per k32: hh=a1b1, mid=a1b0+a0b1 (shared acc); C=(16384hh+128mid)*sAsB.
// CTA 64x128, 256 thr (warps 2m x 4n, warp tile 32x32), BK=32B, 3-stage cp.async.
// mode 0: fp32 C; mode 1: split bf16 Ch/Cl.
// ===========================================================================
__global__ void __launch_bounds__(256, 1)
gemm_i8(const int8_t* __restrict__ A1p, const int8_t* __restrict__ A0p,
        const int8_t* __restrict__ B1p, const int8_t* __restrict__ B0p,
        const float* __restrict__ sA, const float* __restrict__ sB,
        float* __restrict__ C, __nv_bfloat16* __restrict__ Ch, __nv_bfloat16* __restrict__ Cl,
        int Kdim, int lda, int ldb, int ldc,
        long long sAo, long long sAi, long long sBo, long long sBi,
        long long sCo, long long sCi,
        int sSAo, int sSAi, int sSBo, int sSBi,
        int inner, int mode)
{
    constexpr int BM = 64, BN = 128, BK = 32, STAGES = 3;
    constexpr int LDI = 48;                  // bytes per k32 row (32 + 16 pad)
    constexpr int APL = BM * LDI;            // 3072 (one A plane)
    constexpr int BPL = BN * LDI;            // 6144
    constexpr int BOFF = 2 * APL;
    constexpr int STG  = 2 * APL + 2 * BPL;  // 18432 B/stage

    extern __shared__ int8_t smi[];
    const int tid = threadIdx.x, wid = tid >> 5, lane = tid & 31;
    const int g = lane >> 2, t = lane & 3;

    const int z  = blockIdx.z;
    const int zo = z / inner, zi = z - zo * inner;
    const long long aoff = zo * sAo + zi * sAi;
    const long long boff = zo * sBo + zi * sBi;
    const long long coff = zo * sCo + zi * sCi;
    const float* sAb = sA + zo * sSAo + zi * sSAi;
    const float* sBb = sB + zo * sSBo + zi * sSBi;

    const int m0 = blockIdx.y * BM, n0 = blockIdx.x * BN;
    const int wm0 = (wid & 1) * 32, wn0 = (wid >> 1) * 32;
    const uint32_t sbase = smem_u32(smi);

    const int q = lane >> 3;
    const uint32_t a_ln = (uint32_t)(((q & 1) * 8 + (lane & 7)) * LDI + (q >> 1) * 16);
    const uint32_t b_ln = (uint32_t)(((q >> 1) * 8 + (lane & 7)) * LDI + (q & 1) * 16);

    // 768 16B chunks/stage, 3 per thread
    const int8_t* gptr[3]; uint32_t soff[3];
#pragma unroll
    for (int i = 0; i < 3; i++) {
        int c = tid + i * 256;
        if (c < 256) {                     // A: 2 planes x 128 chunks
            int p = c >> 7, cp = c & 127, rr = cp >> 1, off = (cp & 1) * 16;
            gptr[i] = (p == 0 ? A1p : A0p) + aoff + (long long)(m0 + rr) * lda + off;
            soff[i] = (uint32_t)(p * APL + rr * LDI + off);
        } else {                           // B: 2 planes x 256 chunks
            int c2 = c - 256;
            int p = c2 >> 8, cp = c2 & 255, rr = cp >> 1, off = (cp & 1) * 16;
            gptr[i] = (p == 0 ? B1p : B0p) + boff + (long long)(n0 + rr) * ldb + off;
            soff[i] = (uint32_t)(BOFF + p * BPL + rr * LDI + off);
        }
    }

    const int T = Kdim / BK;
    int hh[2][4][4], mid[2][4][4];
#pragma unroll
    for (int i = 0; i < 2; i++)
#pragma unroll
        for (int j = 0; j < 4; j++)
#pragma unroll
            for (int r = 0; r < 4; r++) { hh[i][j][r] = 0; mid[i][j][r] = 0; }

#pragma unroll
    for (int p = 0; p < STAGES - 1; p++) {
        if (p < T) {
            uint32_t sb = sbase + (uint32_t)((p % STAGES) * STG);
#pragma unroll
            for (int i = 0; i < 3; i++) cp_async16(sb + soff[i], gptr[i] + p * BK);
        }
        asm volatile("cp.async.commit_group;" ::: "memory");
    }

    for (int kt = 0; kt < T; kt++) {
        asm volatile("cp.async.wait_group %0;" :: "n"(STAGES - 2) : "memory");
        __syncthreads();
        {
            int tl = kt + STAGES - 1;
            if (tl < T) {
                uint32_t sb = sbase + (uint32_t)((tl % STAGES) * STG);
#pragma unroll
                for (int i = 0; i < 3; i++) cp_async16(sb + soff[i], gptr[i] + tl * BK);
            }
            asm volatile("cp.async.commit_group;" ::: "memory");
        }

        const uint32_t stg = sbase + (uint32_t)((kt % STAGES) * STG);
        uint32_t A1f[2][4], A0f[2][4];
#pragma unroll
        for (int mt = 0; mt < 2; mt++) {
            uint32_t ab = stg + (uint32_t)((wm0 + mt * 16) * LDI) + a_ln;
            LDSM4(A1f[mt], ab);
            LDSM4(A0f[mt], ab + APL);
        }
#pragma unroll
        for (int pr = 0; pr < 2; pr++) {
            uint32_t B1f[4], B0f[4];
            uint32_t bb = stg + (uint32_t)BOFF + (uint32_t)((wn0 + pr * 16) * LDI) + b_ln;
            LDSM4(B1f, bb);
            LDSM4(B0f, bb + BPL);
#pragma unroll
            for (int s = 0; s < 2; s++) {
                const int nt = pr * 2 + s;
#pragma unroll
                for (int mt = 0; mt < 2; mt++) {
                    mma_s8(hh [mt][nt], A1f[mt][0], A1f[mt][1], A1f[mt][2], A1f[mt][3], B1f[2*s], B1f[2*s+1]);
                    mma_s8(mid[mt][nt], A1f[mt][0], A1f[mt][1], A1f[mt][2], A1f[mt][3], B0f[2*s], B0f[2*s+1]);
                    mma_s8(mid[mt][nt], A0f[mt][0], A0f[mt][1], A0f[mt][2], A0f[mt][3], B1f[2*s], B1f[2*s+1]);
                }
            }
        }
    }

#pragma unroll
    for (int mt = 0; mt < 2; mt++) {
        const int r0 = m0 + wm0 + mt * 16 + g;
        const float sa0 = sAb[r0], sa1 = sAb[r0 + 8];
#pragma unroll
        for (int nt = 0; nt < 4; nt++) {
            const int cc = n0 + wn0 + nt * 8 + 2 * t;
            const float sb0 = sBb[cc], sb1 = sBb[cc + 1];
            float v[4];
#pragma unroll
            for (int r = 0; r < 4; r++)
                v[r] = 16384.0f * (float)hh[mt][nt][r] + 128.0f * (float)mid[mt][nt][r];
            float c00 = v[0] * sa0 * sb0, c01 = v[1] * sa0 * sb1;
            float c10 = v[2] * sa1 * sb0, c11 = v[3] * sa1 * sb1;
            if (mode == 0) {
                float2 u0; u0.x = c00; u0.y = c01;
                float2 u1; u1.x = c10; u1.y = c11;
                *(float2*)&C[coff + (long long)r0 * ldc + cc]       = u0;
                *(float2*)&C[coff + (long long)(r0 + 8) * ldc + cc] = u1;
            } else {
                __nv_bfloat16 h0, l0, h1, l1;
                split_bf16(c00, h0, l0); split_bf16(c01, h1, l1);
                __nv_bfloat162 hp; hp.x = h0; hp.y = h1;
                __nv_bfloat162 lp; lp.x = l0; lp.y = l1;
                *(__nv_bfloat162*)&Ch[coff + (long long)r0 * ldc + cc] = hp;
                *(__nv_bfloat162*)&Cl[coff + (long long)r0 * ldc + cc] = lp;
                split_bf16(c10, h0, l0); split_bf16(c11, h1, l1);
                hp.x = h0; hp.y = h1; lp.x = l0; lp.y = l1;
                *(__nv_bfloat162*)&Ch[coff + (long long)(r0 + 8) * ldc + cc] = hp;
                *(__nv_bfloat162*)&Cl[coff + (long long)(r0 + 8) * ldc + cc] = lp;
            }
        }
    }
}

// ===========================================================================
// WIDE 3xBF16 GEMM (proven R6): CTA 128x256, 512 thr, 3 stages.
// ===========================================================================
__global__ void __launch_bounds__(512, 1)
gemm_bf16x3_wide(const __nv_bfloat16* __restrict__ Ah, const __nv_bfloat16* __restrict__ Al,
                 const __nv_bfloat16* __restrict__ Bh, const __nv_bfloat16* __restrict__ Bl,
                 float* __restrict__ C,
                 __nv_bfloat16* __restrict__ Ch, __nv_bfloat16* __restrict__ Cl,
                 int Kdim, int lda, int ldb, int ldc,
                 long long sAo, long long sAi, long long sBo, long long sBi,
                 long long sCo, long long sCi, int inner, float alpha, int mode)
{
    constexpr int BM = 128, BN = 256, BK = 32, STAGES = 3, THREADS = 512;
    constexpr int LDB = 40;
    constexpr int AL_OFF = BM * LDB;
    constexpr int BH_OFF = 2 * BM * LDB;
    constexpr int STG    = 2 * (BM + BN) * LDB;
    constexpr int MT = 2, NPAIR = 4;
    constexpr int A_IT = BM * 4 / THREADS;
    constexpr int B_IT = BN * 4 / THREADS;

    extern __shared__ __nv_bfloat16 sm[];
    const int tid = threadIdx.x, wid = tid >> 5, lane = tid & 31;
    const int g = lane >> 2, t = lane & 3;

    const int z  = blockIdx.z;
    const int zo = z / inner, zi = z - zo * inner;
    Ah += zo * sAo + zi * sAi;  Al += zo * sAo + zi * sAi;
    Bh += zo * sBo + zi * sBi;  Bl += zo * sBo + zi * sBi;
    const long long coff = zo * sCo + zi * sCi;
    const int m0 = blockIdx.y * BM, n0 = blockIdx.x * BN;
    const int wm0 = (wid & 3) * 32, wn0 = (wid >> 2) * 64;
    const uint32_t sbase = smem_u32(sm);

    const int q = lane >> 3;
    const uint32_t a_lane = (uint32_t)(((q & 1) * 8 + (lane & 7)) * LDB * 2 + (q >> 1) * 16);
    const uint32_t b_lane = (uint32_t)(((q >> 1) * 8 + (lane & 7)) * LDB * 2 + (q & 1) * 16);

    int a_go[A_IT]; uint32_t a_sp[A_IT];
#pragma unroll
    for (int i = 0; i < A_IT; i++) {
        int c = tid + i * THREADS;
        int row = c >> 2, kc = (c & 3) * 8;
        a_go[i] = (m0 + row) * lda + kc;
        a_sp[i] = (uint32_t)(row * LDB + kc) * 2u;
    }
    int b_go[B_IT]; uint32_t b_sp[B_IT];
#pragma unroll
    for (int i = 0; i < B_IT; i++) {
        int c = tid + i * THREADS;
        int row = c >> 2, kc = (c & 3) * 8;
        b_go[i] = (n0 + row) * ldb + kc;
        b_sp[i] = (uint32_t)(row * LDB + kc) * 2u;
    }

    const int T = Kdim / BK;
    float acc[MT][8][4];
#pragma unroll
    for (int i = 0; i < MT; i++)
#pragma unroll
        for (int j = 0; j < 8; j++)
#pragma unroll
            for (int r = 0; r < 4; r++) acc[i][j][r] = 0.f;

#pragma unroll
    for (int p = 0; p < STAGES - 1; p++) {
        if (p < T) {
            uint32_t sb = sbase + (uint32_t)((p % STAGES) * STG) * 2u;
#pragma unroll
            for (int i = 0; i < A_IT; i++) {
                cp_async16(sb + a_sp[i], Ah + a_go[i] + p * BK);
                cp_async16(sb + AL_OFF * 2 + a_sp[i], Al + a_go[i] + p * BK);
            }
#pragma unroll
            for (int i = 0; i < B_IT; i++) {
                cp_async16(sb + BH_OFF * 2 + b_sp[i], Bh + b_go[i] + p * BK);
                cp_async16(sb + (BH_OFF + BN * LDB) * 2 + b_sp[i], Bl + b_go[i] + p * BK);
            }
        }
        asm volatile("cp.async.commit_group;" ::: "memory");
    }

    for (int kt = 0; kt < T; kt++) {
        asm volatile("cp.async.wait_group %0;" :: "n"(STAGES - 2) : "memory");
        __syncthreads();
        {
            int tl = kt + STAGES - 1;
            if (tl < T) {
                uint32_t sb = sbase + (uint32_t)((tl % STAGES) * STG) * 2u;
#pragma unroll
                for (int i = 0; i < A_IT; i++) {
                    cp_async16(sb + a_sp[i], Ah + a_go[i] + tl * BK);
                    cp_async16(sb + AL_OFF * 2 + a_sp[i], Al + a_go[i] + tl * BK);
                }
#pragma unroll
                for (int i = 0; i < B_IT; i++) {
                    cp_async16(sb + BH_OFF * 2 + b_sp[i], Bh + b_go[i] + tl * BK);
                    cp_async16(sb + (BH_OFF + BN * LDB) * 2 + b_sp[i], Bl + b_go[i] + tl * BK);
                }
            }
            asm volatile("cp.async.commit_group;" ::: "memory");
        }

        const uint32_t stg = sbase + (uint32_t)((kt % STAGES) * STG) * 2u;
#pragma unroll
        for (int kk = 0; kk < BK; kk += 16) {
            uint32_t ah[MT][4], al[MT][4];
#pragma unroll
            for (int mt = 0; mt < MT; mt++) {
                uint32_t aa = stg + a_lane + (uint32_t)((wm0 + mt * 16) * LDB + kk) * 2u;
                LDSM4(ah[mt], aa);
                LDSM4(al[mt], aa + (uint32_t)(AL_OFF * 2));
            }
#pragma unroll
            for (int pr = 0; pr < NPAIR; pr++) {
                uint32_t bh4[4], bl4[4];
                uint32_t ba = stg + (uint32_t)(BH_OFF * 2) + b_lane
                            + (uint32_t)((wn0 + pr * 16) * LDB + kk) * 2u;
                LDSM4(bh4, ba);
                LDSM4(bl4, ba + (uint32_t)(BN * LDB * 2));
                const int nt0 = pr * 2, nt1 = pr * 2 + 1;
#pragma unroll
                for (int mt = 0; mt < MT; mt++) {
                    mma_bf16(acc[mt][nt0], ah[mt][0], ah[mt][1], ah[mt][2], ah[mt][3], bh4[0], bh4[1]);
                    mma_bf16(acc[mt][nt0], ah[mt][0], ah[mt][1], ah[mt][2], ah[mt][3], bl4[0], bl4[1]);
                    mma_bf16(acc[mt][nt0], al[mt][0], al[mt][1], al[mt][2], al[mt][3], bh4[0], bh4[1]);
                    mma_bf16(acc[mt][nt1], ah[mt][0], ah[mt][1], ah[mt][2], ah[mt][3], bh4[2], bh4[3]);
                    mma_bf16(acc[mt][nt1], ah[mt][0], ah[mt][1], ah[mt][2], ah[mt][3], bl4[2], bl4[3]);
                    mma_bf16(acc[mt][nt1], al[mt][0], al[mt][1], al[mt][2], al[mt][3], bh4[2], bh4[3]);
                }
            }
        }
    }

#pragma unroll
    for (int mt = 0; mt < MT; mt++) {
        const int r0 = m0 + wm0 + mt * 16 + g;
#pragma unroll
        for (int nt = 0; nt < 8; nt++) {
            const int cc = n0 + wn0 + nt * 8 + 2 * t;
            float v00 = acc[mt][nt][0] * alpha, v01 = acc[mt][nt][1] * alpha;
            float v10 = acc[mt][nt][2] * alpha, v11 = acc[mt][nt][3] * alpha;
            if (mode == 0) {
                float2 u0; u0.x = v00; u0.y = v01;
                float2 u1; u1.x = v10; u1.y = v11;
                *(float2*)&C[coff + (long long)r0 * ldc + cc]       = u0;
                *(float2*)&C[coff + (long long)(r0 + 8) * ldc + cc] = u1;
            } else {
                __nv_bfloat16 h0, l0, h1, l1;
                split_bf16(v00, h0, l0); split_bf16(v01, h1, l1);
                __nv_bfloat162 hp; hp.x = h0; hp.y = h1;
                __nv_bfloat162 lp; lp.x = l0; lp.y = l1;
                *(__nv_bfloat162*)&Ch[coff + (long long)r0 * ldc + cc] = hp;
                *(__nv_bfloat162*)&Cl[coff + (long long)r0 * ldc + cc] = lp;
                split_bf16(v10, h0, l0); split_bf16(v11, h1, l1);
                hp.x = h0; hp.y = h1; lp.x = l0; lp.y = l1;
                *(__nv_bfloat162*)&Ch[coff + (long long)(r0 + 8) * ldc + cc] = hp;
                *(__nv_bfloat162*)&Cl[coff + (long long)(r0 + 8) * ldc + cc] = lp;
            }
        }
    }
}

// ===========================================================================
// Narrow 3xBF16 GEMM (BN=64) — proven R4 kernel for Q/K projections.
// ===========================================================================
template<int BN>
__global__ void __launch_bounds__(256)
gemm_bf16x3(const __nv_bfloat16* __restrict__ Ah, const __nv_bfloat16* __restrict__ Al,
            const __nv_bfloat16* __restrict__ Bh, const __nv_bfloat16* __restrict__ Bl,
            __nv_bfloat16* __restrict__ Ch, __nv_bfloat16* __restrict__ Cl,
            int Kdim, int lda, int ldb, int ldc,
            long long sAo, long long sAi, long long sBo, long long sBi,
            long long sCo, long long sCi, int inner)
{
    constexpr int BM = 128, BK = 32, STAGES = 4;
    constexpr int LDB = 40;
    constexpr int AL_OFF = BM * LDB;
    constexpr int BH_OFF = 2 * BM * LDB;
    constexpr int STG    = 2 * (BM + BN) * LDB;
    constexpr int WM = 4;
    constexpr int MT = (BM / WM) / 16;
    constexpr int NT = (BN / 2) / 8;
    constexpr int A_IT = BM * 4 / 256;
    constexpr int B_IT = BN * 4 / 256;

    extern __shared__ __nv_bfloat16 sm[];
    const int tid = threadIdx.x, wid = tid >> 5, lane = tid & 31;
    const int g = lane >> 2, t = lane & 3;

    const int z  = blockIdx.z;
    const int zo = z / inner, zi = z - zo * inner;
    Ah += zo * sAo + zi * sAi;  Al += zo * sAo + zi * sAi;
    Bh += zo * sBo + zi * sBi;  Bl += zo * sBo + zi * sBi;
    const long long coff = zo * sCo + zi * sCi;
    const int m0 = blockIdx.y * BM, n0 = blockIdx.x * BN;
    const int wm0 = (wid % WM) * (BM / WM);
    const int wn0 = (wid / WM) * (BN / 2);
    const uint32_t sbase = smem_u32(sm);

    int a_go[A_IT]; uint32_t a_sp[A_IT];
#pragma unroll
    for (int i = 0; i < A_IT; i++) {
        int c = tid + i * 256;
        int row = c >> 2, kc = (c & 3) * 8;
        a_go[i] = (m0 + row) * lda + kc;
        a_sp[i] = (uint32_t)(row * LDB + kc) * 2u;
    }
    int b_go[B_IT]; uint32_t b_sp[B_IT];
#pragma unroll
    for (int i = 0; i < B_IT; i++) {
        int c = tid + i * 256;
        int row = c >> 2, kc = (c & 3) * 8;
        b_go[i] = (n0 + row) * ldb + kc;
        b_sp[i] = (uint32_t)(row * LDB + kc) * 2u;
    }

    const int T = Kdim / BK;
    float acc[MT][NT][4];
#pragma unroll
    for (int i = 0; i < MT; i++)
#pragma unroll
        for (int j = 0; j < NT; j++)
#pragma unroll
            for (int r = 0; r < 4; r++) acc[i][j][r] = 0.f;

#pragma unroll
    for (int p = 0; p < STAGES - 1; p++) {
        if (p < T) {
            uint32_t sb = sbase + (uint32_t)((p % STAGES) * STG) * 2u;
#pragma unroll
            for (int i = 0; i < A_IT; i++) {
                cp_async16(sb + a_sp[i], Ah + a_go[i] + p * BK);
                cp_async16(sb + AL_OFF * 2 + a_sp[i], Al + a_go[i] + p * BK);
            }
#pragma unroll
            for (int i = 0; i < B_IT; i++) {
                cp_async16(sb + BH_OFF * 2 + b_sp[i], Bh + b_go[i] + p * BK);
                cp_async16(sb + (BH_OFF + BN * LDB) * 2 + b_sp[i], Bl + b_go[i] + p * BK);
            }
        }
        asm volatile("cp.async.commit_group;" ::: "memory");
    }

    for (int kt = 0; kt < T; kt++) {
        asm volatile("cp.async.wait_group %0;" :: "n"(STAGES - 2) : "memory");
        __syncthreads();
        {
            int tl = kt + STAGES - 1;
            if (tl < T) {
                uint32_t sb = sbase + (uint32_t)((tl % STAGES) * STG) * 2u;
#pragma unroll
                for (int i = 0; i < A_IT; i++) {
                    cp_async16(sb + a_sp[i], Ah + a_go[i] + tl * BK);
                    cp_async16(sb + AL_OFF * 2 + a_sp[i], Al + a_go[i] + tl * BK);
                }
#pragma unroll
                for (int i = 0; i < B_IT; i++) {
                    cp_async16(sb + BH_OFF * 2 + b_sp[i], Bh + b_go[i] + tl * BK);
                    cp_async16(sb + (BH_OFF + BN * LDB) * 2 + b_sp[i], Bl + b_go[i] + tl * BK);
                }
            }
            asm volatile("cp.async.commit_group;" ::: "memory");
        }

        const __nv_bfloat16* st = sm + (kt % STAGES) * STG;
        const __nv_bfloat16* sB = st + BH_OFF;
#pragma unroll
        for (int kk = 0; kk < BK; kk += 16) {
            uint32_t bh[NT][2], bl[NT][2];
#pragma unroll
            for (int nt = 0; nt < NT; nt++) {
                const __nv_bfloat16* bp = sB + (wn0 + nt * 8 + g) * LDB + kk + 2 * t;
                bh[nt][0] = lds_u32(bp);
                bh[nt][1] = lds_u32(bp + 8);
                bl[nt][0] = lds_u32(bp + BN * LDB);
                bl[nt][1] = lds_u32(bp + BN * LDB + 8);
            }
#pragma unroll
            for (int mt = 0; mt < MT; mt++) {
                const __nv_bfloat16* ap = st + (wm0 + mt * 16 + g) * LDB + kk + 2 * t;
                uint32_t ah0 = lds_u32(ap);
                uint32_t ah1 = lds_u32(ap + 8 * LDB);
                uint32_t ah2 = lds_u32(ap + 8);
                uint32_t ah3 = lds_u32(ap + 8 * LDB + 8);
                const __nv_bfloat16* alp = ap + AL_OFF;
                uint32_t al0 = lds_u32(alp);
                uint32_t al1 = lds_u32(alp + 8 * LDB);
                uint32_t al2 = lds_u32(alp + 8);
                uint32_t al3 = lds_u32(alp + 8 * LDB + 8);
#pragma unroll
                for (int nt = 0; nt < NT; nt++) {
                    mma_bf16(acc[mt][nt], ah0, ah1, ah2, ah3, bh[nt][0], bh[nt][1]);
                    mma_bf16(acc[mt][nt], ah0, ah1, ah2, ah3, bl[nt][0], bl[nt][1]);
                    mma_bf16(acc[mt][nt], al0, al1, al2, al3, bh[nt][0], bh[nt][1]);
                }
            }
        }
    }

#pragma unroll
    for (int mt = 0; mt < MT; mt++) {
        const int r0 = m0 + wm0 + mt * 16 + g;
#pragma unroll
        for (int nt = 0; nt < NT; nt++) {
            const int cc = n0 + wn0 + nt * 8 + 2 * t;
            __nv_bfloat16 h0, l0, h1, l1;
            split_bf16(acc[mt][nt][0], h0, l0); split_bf16(acc[mt][nt][1], h1, l1);
            __nv_bfloat162 hp; hp.x = h0; hp.y = h1;
            __nv_bfloat162 lp; lp.x = l0; lp.y = l1;
            *(__nv_bfloat162*)&Ch[coff + (long long)r0 * ldc + cc] = hp;
            *(__nv_bfloat162*)&Cl[coff + (long long)r0 * ldc + cc] = lp;
            split_bf16(acc[mt][nt][2], h0, l0); split_bf16(acc[mt][nt][3], h1, l1);
            hp.x = h0; hp.y = h1; lp.x = l0; lp.y = l1;
            *(__nv_bfloat162*)&Ch[coff + (long long)(r0 + 8) * ldc + cc] = hp;
            *(__nv_bfloat162*)&Cl[coff + (long long)(r0 + 8) * ldc + cc] = lp;
        }
    }
}

// ---------------- elementwise kernels ----------------
__global__ void split_copy_kernel(const float4* __restrict__ in,
                                  __nv_bfloat16* __restrict__ oh,
                                  __nv_bfloat16* __restrict__ ol, int n4)
{
    int i = blockIdx.x * blockDim.x + threadIdx.x;
    if (i < n4) {
        float4 v = in[i];
        __nv_bfloat16 h, l;
        __nv_bfloat162 h01, h23, l01, l23;
        split_bf16(v.x, h, l); h01.x = h; l01.x = l;
        split_bf16(v.y, h, l); h01.y = h; l01.y = l;
        split_bf16(v.z, h, l); h23.x = h; l23.x = l;
        split_bf16(v.w, h, l); h23.y = h; l23.y = l;
        ((__nv_bfloat162*)oh)[2 * i] = h01; ((__nv_bfloat162*)oh)[2 * i + 1] = h23;
        ((__nv_bfloat162*)ol)[2 * i] = l01; ((__nv_bfloat162*)ol)[2 * i + 1] = l23;
    }
}

__global__ void transpose_split_kernel(const float* __restrict__ in,
                                       __nv_bfloat16* __restrict__ oh,
                                       __nv_bfloat16* __restrict__ ol,
                                       int ldi, int ldo,
                                       long long sIo, long long sIi,
                                       long long sOo, long long sOi, int inner)
{
    __shared__ float tile[32][33];
    const int z  = blockIdx.z;
    const int zo = z / inner, zi = z - zo * inner;
    const float* ip = in + zo * sIo + zi * sIi;
    const long long oo = zo * sOo + zi * sOi;
    const int c0 = blockIdx.x * 32, r0 = blockIdx.y * 32;
    const int tx = threadIdx.x, ty = threadIdx.y;
#pragma unroll
    for (int i = 0; i < 32; i += 8)
        tile[ty + i][tx] = ip[(long long)(r0 + ty + i) * ldi + c0 + tx];
    __syncthreads();
#pragma unroll
    for (int i = 0; i < 32; i += 8) {
        __nv_bfloat16 h, l;
        split_bf16(tile[tx][ty + i], h, l);
        long long o = oo + (long long)(c0 + ty + i) * ldo + r0 + tx;
        oh[o] = h; ol[o] = l;
    }
}

// 32x32 tile transpose -> 2-plane int8, scale per OUTPUT row (scale[zo*1024+row])
__global__ void quant_transpose_kernel(const float* __restrict__ in,
                                       int8_t* __restrict__ p1, int8_t* __restrict__ p0,
                                       const float* __restrict__ scale,
                                       int ldi, int ldo,
                                       long long sIo, long long sIi,
                                       long long sOo, long long sOi, int inner)
{
    __shared__ float tile[32][33];
    const int z  = blockIdx.z;
    const int zo = z / inner, zi = z - zo * inner;
    const float* ip = in + zo * sIo + zi * sIi;
    const long long oo = zo * sOo + zi * sOi;
    const int c0 = blockIdx.x * 32, r0 = blockIdx.y * 32;
    const int tx = threadIdx.x, ty = threadIdx.y;
#pragma unroll
    for (int i = 0; i < 32; i += 8)
        tile[ty + i][tx] = ip[(long long)(r0 + ty + i) * ldi + c0 + tx];
    __syncthreads();
#pragma unroll
    for (int i = 0; i < 32; i += 8) {
        const int orow = c0 + ty + i;
        const float inv = 1.0f / scale[zo * 1024 + orow];
        int8_t q1, q0;
        quant2(tile[tx][ty + i], inv, q1, q0);
        long long o = oo + (long long)orow * ldo + r0 + tx;
        p1[o] = q1; p0[o] = q0;
    }
}

// per-row absmax/16256 over contiguous rows of width K. one block per row.
__global__ void rowmax_kernel(const float* __restrict__ in, float* __restrict__ s, int K)
{
    __shared__ float red[8];
    const long long row = (long long)blockIdx.x * K;
    const int tid = threadIdx.x, lane = tid & 31, warp = tid >> 5;
    float m = 0.f;
    for (int i = tid; i < K / 4; i += 256) {
        float4 v = ((const float4*)(in + row))[i];
        m = fmaxf(m, fmaxf(fmaxf(fabsf(v.x), fabsf(v.y)), fmaxf(fabsf(v.z), fabsf(v.w))));
    }
#pragma unroll
    for (int o = 16; o; o >>= 1) m = fmaxf(m, __shfl_xor_sync(0xffffffffu, m, o));
    if (lane == 0) red[warp] = m;
    __syncthreads();
    if (tid == 0) {
#pragma unroll
        for (int j = 1; j < 8; j++) m = fmaxf(m, red[j]);
        s[blockIdx.x] = fmaxf(m, 1e-30f) * (1.0f / 16256.0f);
    }
}

// per-column absmax/16256 over R rows of width 1024, per z.
__global__ void colmax_kernel(const float* __restrict__ in, float* __restrict__ s, int R)
{
    const int z = blockIdx.y;
    const int c = blockIdx.x * 256 + threadIdx.x;
    const float* ip = in + (long long)z * R * 1024 + c;
    float m = 0.f;
    for (int r = 0; r < R; r++) m = fmaxf(m, fabsf(ip[(long long)r * 1024]));
    s[z * 1024 + c] = fmaxf(m, 1e-30f) * (1.0f / 16256.0f);
}

// quantize contiguous rows into 2 int8 planes (row = i4/(K/4)).
__global__ void rowquant_kernel(const float4* __restrict__ in,
                                int8_t* __restrict__ p1, int8_t* __restrict__ p0,
                                const float* __restrict__ s, int K4, long long n4)
{
    long long i = (long long)blockIdx.x * blockDim.x + threadIdx.x;
    if (i < n4) {
        const float inv = 1.0f / s[i / K4];
        float4 v = in[i];
        char4 q1, q0;
        quant2(v.x, inv, (int8_t&)q1.x, (int8_t&)q0.x);
        quant2(v.y, inv, (int8_t&)q1.y, (int8_t&)q0.y);
        quant2(v.z, inv, (int8_t&)q1.z, (int8_t&)q0.z);
        quant2(v.w, inv, (int8_t&)q1.w, (int8_t&)q0.w);
        ((char4*)p1)[i] = q1; ((char4*)p0)[i] = q0;
    }
}

// softmax rows (fp32 in, bf16 hi/lo out), one block per 1024-wide row
__global__ void softmax_split_kernel(const float* __restrict__ Sf,
                                     __nv_bfloat16* __restrict__ Sh,
                                     __nv_bfloat16* __restrict__ Sl)
{
    __shared__ float red[8];
    const long long row = (long long)blockIdx.x * N_;
    const float4* p = (const float4*)(Sf + row);
    const int tid = threadIdx.x, lane = tid & 31, warp = tid >> 5;
    float4 x = p[tid];
    float m = fmaxf(fmaxf(x.x, x.y), fmaxf(x.z, x.w));
#pragma unroll
    for (int o = 16; o; o >>= 1) m = fmaxf(m, __shfl_xor_sync(0xffffffffu, m, o));
    if (lane == 0) red[warp] = m;
    __syncthreads();
    m = red[0];
#pragma unroll
    for (int j = 1; j < 8; j++) m = fmaxf(m, red[j]);
    __syncthreads();
    x.x = __expf(x.x - m); x.y = __expf(x.y - m);
    x.z = __expf(x.z - m); x.w = __expf(x.w - m);
    float s = x.x + x.y + x.z + x.w;
#pragma unroll
    for (int o = 16; o; o >>= 1) s += __shfl_xor_sync(0xffffffffu, s, o);
    if (lane == 0) red[warp] = s;
    __syncthreads();
    s = red[0];
#pragma unroll
    for (int j = 1; j < 8; j++) s += red[j];
    const float inv = 1.0f / s;
    __nv_bfloat16 h, l;
    __nv_bfloat162 h01, h23, l01, l23;
    split_bf16(x.x * inv, h, l); h01.x = h; l01.x = l;
    split_bf16(x.y * inv, h, l); h01.y = h; l01.y = l;
    split_bf16(x.z * inv, h, l); h23.x = h; l23.x = l;
    split_bf16(x.w * inv, h, l); h23.y = h; l23.y = l;
    ((__nv_bfloat162*)(Sh + row))[2 * tid]     = h01;
    ((__nv_bfloat162*)(Sh + row))[2 * tid + 1] = h23;
    ((__nv_bfloat162*)(Sl + row))[2 * tid]     = l01;
    ((__nv_bfloat162*)(Sl + row))[2 * tid + 1] = l23;
}

// ---------------- launch ----------------
extern "C" void kernel_launch(void* const* d_in, const int* in_sizes, int n_in,
                              void* d_out, int out_size)
{
    (void)in_sizes; (void)n_in; (void)out_size;
    const float* query = (const float*)d_in[0];
    const float* key   = (const float*)d_in[1];
    const float* value = (const float*)d_in[2];
    const float* w_q   = (const float*)d_in[3];
    const float* w_k   = (const float*)d_in[4];
    const float* w_v   = (const float*)d_in[5];
    const float* w_o   = (const float*)d_in[6];
    float*       out   = (float*)d_out;

    __nv_bfloat16 *qh, *ql, *kh, *kl, *wqTh, *wqTl, *wkTh, *wkTl;
    __nv_bfloat16 *Qh, *Ql, *Kh, *Kl, *Sh, *Sl, *Vth, *Vtl;
    float *Sf, *Of, *sv, *swv, *swo, *sp;
    int8_t *v1, *v0, *wv1, *wv0, *wo1, *wo0, *P1, *P0;
    cudaGetSymbolAddress((void**)&qh, g_qh);   cudaGetSymbolAddress((void**)&ql, g_ql);
    cudaGetSymbolAddress((void**)&kh, g_kh);   cudaGetSymbolAddress((void**)&kl, g_kl);
    cudaGetSymbolAddress((void**)&wqTh, g_wqTh); cudaGetSymbolAddress((void**)&wqTl, g_wqTl);
    cudaGetSymbolAddress((void**)&wkTh, g_wkTh); cudaGetSymbolAddress((void**)&wkTl, g_wkTl);
    cudaGetSymbolAddress((void**)&Qh, g_Qh);   cudaGetSymbolAddress((void**)&Ql, g_Ql);
    cudaGetSymbolAddress((void**)&Kh, g_Kh);   cudaGetSymbolAddress((void**)&Kl, g_Kl);
    cudaGetSymbolAddress((void**)&Sf, g_Sf);
    cudaGetSymbolAddress((void**)&Sh, g_Sh);   cudaGetSymbolAddress((void**)&Sl, g_Sl);
    cudaGetSymbolAddress((void**)&Vth, g_Vth); cudaGetSymbolAddress((void**)&Vtl, g_Vtl);
    cudaGetSymbolAddress((void**)&Of, g_Of);
    cudaGetSymbolAddress((void**)&v1, g_v1);   cudaGetSymbolAddress((void**)&v0, g_v0);
    cudaGetSymbolAddress((void**)&sv, g_sv);
    cudaGetSymbolAddress((void**)&wv1, g_wv1); cudaGetSymbolAddress((void**)&wv0, g_wv0);
    cudaGetSymbolAddress((void**)&swv, g_swv);
    cudaGetSymbolAddress((void**)&wo1, g_wo1); cudaGetSymbolAddress((void**)&wo0, g_wo0);
    cudaGetSymbolAddress((void**)&swo, g_swo);
    cudaGetSymbolAddress((void**)&P1, g_P1);   cudaGetSymbolAddress((void**)&P0, g_P0);
    cudaGetSymbolAddress((void**)&sp, g_sp);

    constexpr int SMEM_W  = 3 * 2 * (128 + 256) * 40 * 2;   // 184320
    constexpr int SMEM_64 = 4 * 2 * (128 + 64)  * 40 * 2;   // 122880
    constexpr int SMEM_I8 = 3 * (2 * 64 * 48 + 2 * 128 * 48); // 55296
    cudaFuncSetAttribute(gemm_bf16x3_wide, cudaFuncAttributeMaxDynamicSharedMemorySize, SMEM_W);
    cudaFuncSetAttribute(gemm_bf16x3<64>,  cudaFuncAttributeMaxDynamicSharedMemorySize, SMEM_64);
    cudaFuncSetAttribute(gemm_i8,          cudaFuncAttributeMaxDynamicSharedMemorySize, SMEM_I8);

    const long long MB = 1024LL * 1024LL;
    const int ZBH = B_ * H_;

    // 0-3: quantize value + w_v
    rowmax_kernel<<<B_ * N_, 256>>>(value, sv, DM_);
    rowquant_kernel<<<(B_ * N_ * DM_ / 4 + 255) / 256, 256>>>(
        (const float4*)value, v1, v0, sv, DM_ / 4, (long long)B_ * N_ * DM_ / 4);
    colmax_kernel<<<dim3(4, H_), 256>>>(w_v, swv, DM_);
    quant_transpose_kernel<<<dim3(DV_ / 32, DM_ / 32, H_), dim3(32, 8)>>>(
        w_v, wv1, wv0, swv, DV_, DM_, (long long)DM_ * DV_, 0, (long long)DV_ * DM_, 0, 1);
    // 4
    split_copy_kernel<<<(B_ * N_ * DM_ / 4 + 255) / 256, 256>>>((const float4*)query, qh, ql, B_ * N_ * DM_ / 4);
    // 5: int8 V-proj -> Vt split  (ncu -s 5 profiles this)
    gemm_i8<<<dim3(8, 16, ZBH), 256, SMEM_I8>>>(
        wv1, wv0, v1, v0, swv, sv, nullptr, Vth, Vtl,
        DM_, DM_, DM_, N_,
        0, (long long)DV_ * DM_,
        (long long)N_ * DM_, 0,
        (long long)H_ * DV_ * N_, (long long)DV_ * N_,
        0, DV_, N_, 0,
        H_, 1);
    // 6-8: remaining prep
    split_copy_kernel<<<(B_ * N_ * DM_ / 4 + 255) / 256, 256>>>((const float4*)key, kh, kl, B_ * N_ * DM_ / 4);
    transpose_split_kernel<<<dim3(DK_ / 32, DM_ / 32, H_), dim3(32, 8)>>>(
        w_q, wqTh, wqTl, DK_, DM_, (long long)DM_ * DK_, 0, (long long)DK_ * DM_, 0, 1);
    transpose_split_kernel<<<dim3(DK_ / 32, DM_ / 32, H_), dim3(32, 8)>>>(
        w_k, wkTh, wkTl, DK_, DM_, (long long)DM_ * DK_, 0, (long long)DK_ * DM_, 0, 1);
    // 9-10: Q/K projections (bf16 3x)
    gemm_bf16x3<64><<<dim3(1, 8, ZBH), 256, SMEM_64>>>(
        qh, ql, wqTh, wqTl, Qh, Ql, DM_, DM_, DM_, DK_,
        (long long)N_ * DM_, 0, 0, (long long)DK_ * DM_,
        (long long)H_ * N_ * DK_, (long long)N_ * DK_, H_);
    gemm_bf16x3<64><<<dim3(1, 8, ZBH), 256, SMEM_64>>>(
        kh, kl, wkTh, wkTl, Kh, Kl, DM_, DM_, DM_, DK_,
        (long long)N_ * DM_, 0, 0, (long long)DK_ * DM_,
        (long long)H_ * N_ * DK_, (long long)N_ * DK_, H_);
    // 11: scores (bf16 3x wide), 12: softmax
    gemm_bf16x3_wide<<<dim3(4, 8, ZBH), 512, SMEM_W>>>(
        Qh, Ql, Kh, Kl, Sf, nullptr, nullptr, DK_, DK_, DK_, N_,
        (long long)N_ * DK_, 0, (long long)N_ * DK_, 0, (long long)N_ * N_, 0,
        1, 0.125f, 0);
    softmax_split_kernel<<<ZBH * N_, 256>>>(Sf, Sh, Sl);
    // 13: S·V (bf16 3x wide) -> Of
    gemm_bf16x3_wide<<<dim3(4, 8, ZBH), 512, SMEM_W>>>(
        Sh, Sl, Vth, Vtl, Of, nullptr, nullptr, N_, N_, N_, DV_,
        (long long)N_ * N_, 0, (long long)DV_ * N_, 0, (long long)N_ * DV_, 0,
        1, 1.0f, 0);
    // 14-17: quantize O->P and w_o
    colmax_kernel<<<dim3(4, B_), 256>>>(Of, sp, H_ * N_);
    quant_transpose_kernel<<<dim3(32, 32, ZBH), dim3(32, 8)>>>(
        Of, P1, P0, sp, DV_, H_ * N_,
        (long long)H_ * MB, MB, (long long)H_ * MB, (long long)N_, H_);
    rowmax_kernel<<<DM_, 256>>>(w_o, swo, H_ * DV_);
    rowquant_kernel<<<(DM_ * H_ * DV_ / 4 + 255) / 256, 256>>>(
        (const float4*)w_o, wo1, wo0, swo, H_ * DV_ / 4, (long long)DM_ * H_ * DV_ / 4);
    // 18: int8 w_o GEMM -> out (fp32), K=16384
    gemm_i8<<<dim3(8, 16, B_), 256, SMEM_I8>>>(
        wo1, wo0, P1, P0, swo, sp, out, nullptr, nullptr,
        H_ * N_, H_ * N_, H_ * N_, DV_,
        0, 0, (long long)DV_ * H_ * N_, 0, (long long)DM_ * DV_, 0,
        0, 0, DV_, 0,
        1, 0);
}

// round 10
// speedup vs baseline: 1.0018x; 1.0018x over previous
#include <cuda_runtime.h>
#include <cuda_bf16.h>
#include <cstdint>

#define B_   4
#define N_   1024
#define DM_  1024
#define H_   16
#define DK_  64
#define DV_  1024

// ---------------- scratch (device globals) ----------------
__device__ __nv_bfloat16 g_qh [B_ * N_ * DM_],  g_ql [B_ * N_ * DM_];
__device__ __nv_bfloat16 g_kh [B_ * N_ * DM_],  g_kl [B_ * N_ * DM_];
__device__ __nv_bfloat16 g_wqTh[H_ * DK_ * DM_], g_wqTl[H_ * DK_ * DM_];
__device__ __nv_bfloat16 g_wkTh[H_ * DK_ * DM_], g_wkTl[H_ * DK_ * DM_];
__device__ __nv_bfloat16 g_Qh [B_ * H_ * N_ * DK_], g_Ql [B_ * H_ * N_ * DK_];
__device__ __nv_bfloat16 g_Kh [B_ * H_ * N_ * DK_], g_Kl [B_ * H_ * N_ * DK_];
__device__ float         g_Sf [B_ * H_ * N_ * N_];
__device__ __nv_bfloat16 g_Sh [B_ * H_ * N_ * N_],  g_Sl [B_ * H_ * N_ * N_];
__device__ __nv_bfloat16 g_Vth[B_ * H_ * DV_ * N_], g_Vtl[B_ * H_ * DV_ * N_];
__device__ float         g_Of [B_ * H_ * N_ * DV_];
// int8 limb planes + scales
__device__ int8_t g_v1 [B_ * N_ * DM_],   g_v0 [B_ * N_ * DM_];
__device__ float  g_sv [B_ * N_];
__device__ int8_t g_wv1[H_ * DV_ * DM_],  g_wv0[H_ * DV_ * DM_];
__device__ float  g_swv[H_ * DV_];
__device__ int8_t g_wo1[DM_ * H_ * DV_],  g_wo0[DM_ * H_ * DV_];
__device__ float  g_swo[DM_];
__device__ int8_t g_P1 [B_ * DV_ * H_ * N_], g_P0 [B_ * DV_ * H_ * N_];
__device__ float  g_sp [B_ * DV_];

// ---------------- helpers ----------------
__device__ __forceinline__ uint32_t smem_u32(const void* p) {
    uint32_t a;
    asm("{ .reg .u64 t; cvta.to.shared.u64 t, %1; cvt.u32.u64 %0, t; }" : "=r"(a) : "l"(p));
    return a;
}
__device__ __forceinline__ void split_bf16(float x, __nv_bfloat16& h, __nv_bfloat16& l) {
    h = __float2bfloat16_rn(x);
    l = __float2bfloat16_rn(x - __bfloat162float(h));
}
__device__ __forceinline__ void cp_async16(uint32_t saddr, const void* gptr) {
    asm volatile("cp.async.cg.shared.global [%0], [%1], 16;" :: "r"(saddr), "l"(gptr));
}
__device__ __forceinline__ uint32_t lds_u32(const __nv_bfloat16* p) {
    return *reinterpret_cast<const uint32_t*>(p);
}
__device__ __forceinline__ void mma_bf16(float* c,
    uint32_t a0, uint32_t a1, uint32_t a2, uint32_t a3, uint32_t b0, uint32_t b1) {
    asm volatile(
        "mma.sync.aligned.m16n8k16.row.col.f32.bf16.bf16.f32 "
        "{%0,%1,%2,%3}, {%4,%5,%6,%7}, {%8,%9}, {%0,%1,%2,%3};"
        : "+f"(c[0]), "+f"(c[1]), "+f"(c[2]), "+f"(c[3])
        : "r"(a0), "r"(a1), "r"(a2), "r"(a3), "r"(b0), "r"(b1));
}
__device__ __forceinline__ void mma_s8(int* c,
    uint32_t a0, uint32_t a1, uint32_t a2, uint32_t a3, uint32_t b0, uint32_t b1) {
    asm volatile(
        "mma.sync.aligned.m16n8k32.row.col.s32.s8.s8.s32 "
        "{%0,%1,%2,%3}, {%4,%5,%6,%7}, {%8,%9}, {%0,%1,%2,%3};"
        : "+r"(c[0]), "+r"(c[1]), "+r"(c[2]), "+r"(c[3])
        : "r"(a0), "r"(a1), "r"(a2), "r"(a3), "r"(b0), "r"(b1));
}
#define LDSM4(r, addr) \
    asm volatile("ldmatrix.sync.aligned.m8n8.x4.shared.b16 {%0,%1,%2,%3}, [%4];" \
        : "=r"((r)[0]), "=r"((r)[1]), "=r"((r)[2]), "=r"((r)[3]) : "r"(addr))

// x ~= (128*q1 + q0) * s exactly over the 14.x-bit grid, |t|<=16256
__device__ __forceinline__ void quant2(float x, float inv, int8_t& q1, int8_t& q0) {
    float t = rintf(x * inv);
    int i1 = __float2int_rn(t * (1.0f / 128.0f));
    int i0 = __float2int_rn(t) - (i1 << 7);
    q1 = (int8_t)i1; q0 = (int8_t)i0;
}

// ===========================================================================
// INT8 2-limb GEMM: C[m,n] = sum_k A[m,k]*B[n,k],  A=(128a1+a0)sA[m], B likewise.
// 3 IMMA per k32: hh=a1b1, mid=a1b0+a0b1 (shared acc); C=(16384hh+128mid)*sAsB.
// CTA 64x128, 256 thr (warps 2m x 4n, warp tile 32x32), BK=32B, 3-stage cp.async.
// mode 0: fp32 C; mode 1: split bf16 Ch/Cl.
// ===========================================================================
__global__ void __launch_bounds__(256, 1)
gemm_i8(const int8_t* __restrict__ A1p, const int8_t* __restrict__ A0p,
        const int8_t* __restrict__ B1p, const int8_t* __restrict__ B0p,
        const float* __restrict__ sA, const float* __restrict__ sB,
        float* __restrict__ C, __nv_bfloat16* __restrict__ Ch, __nv_bfloat16* __restrict__ Cl,
        int Kdim, int lda, int ldb, int ldc,
        long long sAo, long long sAi, long long sBo, long long sBi,
        long long sCo, long long sCi,
        int sSAo, int sSAi, int sSBo, int sSBi,
        int inner, int mode)
{
    constexpr int BM = 64, BN = 128, BK = 32, STAGES = 3;
    constexpr int LDI = 48;                  // bytes per k32 row (32 + 16 pad)
    constexpr int APL = BM * LDI;            // 3072 (one A plane)
    constexpr int BPL = BN * LDI;            // 6144
    constexpr int BOFF = 2 * APL;
    constexpr int STG  = 2 * APL + 2 * BPL;  // 18432 B/stage

    extern __shared__ int8_t smi[];
    const int tid = threadIdx.x, wid = tid >> 5, lane = tid & 31;
    const int g = lane >> 2, t = lane & 3;

    const int z  = blockIdx.z;
    const int zo = z / inner, zi = z - zo * inner;
    const long long aoff = zo * sAo + zi * sAi;
    const long long boff = zo * sBo + zi * sBi;
    const long long coff = zo * sCo + zi * sCi;
    const float* sAb = sA + zo * sSAo + zi * sSAi;
    const float* sBb = sB + zo * sSBo + zi * sSBi;

    const int m0 = blockIdx.y * BM, n0 = blockIdx.x * BN;
    const int wm0 = (wid & 1) * 32, wn0 = (wid >> 1) * 32;
    const uint32_t sbase = smem_u32(smi);

    const int q = lane >> 3;
    const uint32_t a_ln = (uint32_t)(((q & 1) * 8 + (lane & 7)) * LDI + (q >> 1) * 16);
    const uint32_t b_ln = (uint32_t)(((q >> 1) * 8 + (lane & 7)) * LDI + (q & 1) * 16);

    // 768 16B chunks/stage, 3 per thread
    const int8_t* gptr[3]; uint32_t soff[3];
#pragma unroll
    for (int i = 0; i < 3; i++) {
        int c = tid + i * 256;
        if (c < 256) {                     // A: 2 planes x 128 chunks
            int p = c >> 7, cp = c & 127, rr = cp >> 1, off = (cp & 1) * 16;
            gptr[i] = (p == 0 ? A1p : A0p) + aoff + (long long)(m0 + rr) * lda + off;
            soff[i] = (uint32_t)(p * APL + rr * LDI + off);
        } else {                           // B: 2 planes x 256 chunks
            int c2 = c - 256;
            int p = c2 >> 8, cp = c2 & 255, rr = cp >> 1, off = (cp & 1) * 16;
            gptr[i] = (p == 0 ? B1p : B0p) + boff + (long long)(n0 + rr) * ldb + off;
            soff[i] = (uint32_t)(BOFF + p * BPL + rr * LDI + off);
        }
    }

    const int T = Kdim / BK;
    int hh[2][4][4], mid[2][4][4];
#pragma unroll
    for (int i = 0; i < 2; i++)
#pragma unroll
        for (int j = 0; j < 4; j++)
#pragma unroll
            for (int r = 0; r < 4; r++) { hh[i][j][r] = 0; mid[i][j][r] = 0; }

#pragma unroll
    for (int p = 0; p < STAGES - 1; p++) {
        if (p < T) {
            uint32_t sb = sbase + (uint32_t)((p % STAGES) * STG);
#pragma unroll
            for (int i = 0; i < 3; i++) cp_async16(sb + soff[i], gptr[i] + p * BK);
        }
        asm volatile("cp.async.commit_group;" ::: "memory");
    }

    for (int kt = 0; kt < T; kt++) {
        asm volatile("cp.async.wait_group %0;" :: "n"(STAGES - 2) : "memory");
        __syncthreads();
        {
            int tl = kt + STAGES - 1;
            if (tl < T) {
                uint32_t sb = sbase + (uint32_t)((tl % STAGES) * STG);
#pragma unroll
                for (int i = 0; i < 3; i++) cp_async16(sb + soff[i], gptr[i] + tl * BK);
            }
            asm volatile("cp.async.commit_group;" ::: "memory");
        }

        const uint32_t stg = sbase + (uint32_t)((kt % STAGES) * STG);
        uint32_t A1f[2][4], A0f[2][4];
#pragma unroll
        for (int mt = 0; mt < 2; mt++) {
            uint32_t ab = stg + (uint32_t)((wm0 + mt * 16) * LDI) + a_ln;
            LDSM4(A1f[mt], ab);
            LDSM4(A0f[mt], ab + APL);
        }
#pragma unroll
        for (int pr = 0; pr < 2; pr++) {
            uint32_t B1f[4], B0f[4];
            uint32_t bb = stg + (uint32_t)BOFF + (uint32_t)((wn0 + pr * 16) * LDI) + b_ln;
            LDSM4(B1f, bb);
            LDSM4(B0f, bb + BPL);
#pragma unroll
            for (int s = 0; s < 2; s++) {
                const int nt = pr * 2 + s;
#pragma unroll
                for (int mt = 0; mt < 2; mt++) {
                    mma_s8(hh [mt][nt], A1f[mt][0], A1f[mt][1], A1f[mt][2], A1f[mt][3], B1f[2*s], B1f[2*s+1]);
                    mma_s8(mid[mt][nt], A1f[mt][0], A1f[mt][1], A1f[mt][2], A1f[mt][3], B0f[2*s], B0f[2*s+1]);
                    mma_s8(mid[mt][nt], A0f[mt][0], A0f[mt][1], A0f[mt][2], A0f[mt][3], B1f[2*s], B1f[2*s+1]);
                }
            }
        }
    }

#pragma unroll
    for (int mt = 0; mt < 2; mt++) {
        const int r0 = m0 + wm0 + mt * 16 + g;
        const float sa0 = sAb[r0], sa1 = sAb[r0 + 8];
#pragma unroll
        for (int nt = 0; nt < 4; nt++) {
            const int cc = n0 + wn0 + nt * 8 + 2 * t;
            const float sb0 = sBb[cc], sb1 = sBb[cc + 1];
            float v[4];
#pragma unroll
            for (int r = 0; r < 4; r++)
                v[r] = 16384.0f * (float)hh[mt][nt][r] + 128.0f * (float)mid[mt][nt][r];
            float c00 = v[0] * sa0 * sb0, c01 = v[1] * sa0 * sb1;
            float c10 = v[2] * sa1 * sb0, c11 = v[3] * sa1 * sb1;
            if (mode == 0) {
                float2 u0; u0.x = c00; u0.y = c01;
                float2 u1; u1.x = c10; u1.y = c11;
                *(float2*)&C[coff + (long long)r0 * ldc + cc]       = u0;
                *(float2*)&C[coff + (long long)(r0 + 8) * ldc + cc] = u1;
            } else {
                __nv_bfloat16 h0, l0, h1, l1;
                split_bf16(c00, h0, l0); split_bf16(c01, h1, l1);
                __nv_bfloat162 hp; hp.x = h0; hp.y = h1;
                __nv_bfloat162 lp; lp.x = l0; lp.y = l1;
                *(__nv_bfloat162*)&Ch[coff + (long long)r0 * ldc + cc] = hp;
                *(__nv_bfloat162*)&Cl[coff + (long long)r0 * ldc + cc] = lp;
                split_bf16(c10, h0, l0); split_bf16(c11, h1, l1);
                hp.x = h0; hp.y = h1; lp.x = l0; lp.y = l1;
                *(__nv_bfloat162*)&Ch[coff + (long long)(r0 + 8) * ldc + cc] = hp;
                *(__nv_bfloat162*)&Cl[coff + (long long)(r0 + 8) * ldc + cc] = lp;
            }
        }
    }
}

// ===========================================================================
// WIDE 3xBF16 GEMM (proven R6): CTA 128x256, 512 thr, 3 stages.
// ===========================================================================
__global__ void __launch_bounds__(512, 1)
gemm_bf16x3_wide(const __nv_bfloat16* __restrict__ Ah, const __nv_bfloat16* __restrict__ Al,
                 const __nv_bfloat16* __restrict__ Bh, const __nv_bfloat16* __restrict__ Bl,
                 float* __restrict__ C,
                 __nv_bfloat16* __restrict__ Ch, __nv_bfloat16* __restrict__ Cl,
                 int Kdim, int lda, int ldb, int ldc,
                 long long sAo, long long sAi, long long sBo, long long sBi,
                 long long sCo, long long sCi, int inner, float alpha, int mode)
{
    constexpr int BM = 128, BN = 256, BK = 32, STAGES = 3, THREADS = 512;
    constexpr int LDB = 40;
    constexpr int AL_OFF = BM * LDB;
    constexpr int BH_OFF = 2 * BM * LDB;
    constexpr int STG    = 2 * (BM + BN) * LDB;
    constexpr int MT = 2, NPAIR = 4;
    constexpr int A_IT = BM * 4 / THREADS;
    constexpr int B_IT = BN * 4 / THREADS;

    extern __shared__ __nv_bfloat16 sm[];
    const int tid = threadIdx.x, wid = tid >> 5, lane = tid & 31;
    const int g = lane >> 2, t = lane & 3;

    const int z  = blockIdx.z;
    const int zo = z / inner, zi = z - zo * inner;
    Ah += zo * sAo + zi * sAi;  Al += zo * sAo + zi * sAi;
    Bh += zo * sBo + zi * sBi;  Bl += zo * sBo + zi * sBi;
    const long long coff = zo * sCo + zi * sCi;
    const int m0 = blockIdx.y * BM, n0 = blockIdx.x * BN;
    const int wm0 = (wid & 3) * 32, wn0 = (wid >> 2) * 64;
    const uint32_t sbase = smem_u32(sm);

    const int q = lane >> 3;
    const uint32_t a_lane = (uint32_t)(((q & 1) * 8 + (lane & 7)) * LDB * 2 + (q >> 1) * 16);
    const uint32_t b_lane = (uint32_t)(((q >> 1) * 8 + (lane & 7)) * LDB * 2 + (q & 1) * 16);

    int a_go[A_IT]; uint32_t a_sp[A_IT];
#pragma unroll
    for (int i = 0; i < A_IT; i++) {
        int c = tid + i * THREADS;
        int row = c >> 2, kc = (c & 3) * 8;
        a_go[i] = (m0 + row) * lda + kc;
        a_sp[i] = (uint32_t)(row * LDB + kc) * 2u;
    }
    int b_go[B_IT]; uint32_t b_sp[B_IT];
#pragma unroll
    for (int i = 0; i < B_IT; i++) {
        int c = tid + i * THREADS;
        int row = c >> 2, kc = (c & 3) * 8;
        b_go[i] = (n0 + row) * ldb + kc;
        b_sp[i] = (uint32_t)(row * LDB + kc) * 2u;
    }

    const int T = Kdim / BK;
    float acc[MT][8][4];
#pragma unroll
    for (int i = 0; i < MT; i++)
#pragma unroll
        for (int j = 0; j < 8; j++)
#pragma unroll
            for (int r = 0; r < 4; r++) acc[i][j][r] = 0.f;

#pragma unroll
    for (int p = 0; p < STAGES - 1; p++) {
        if (p < T) {
            uint32_t sb = sbase + (uint32_t)((p % STAGES) * STG) * 2u;
#pragma unroll
            for (int i = 0; i < A_IT; i++) {
                cp_async16(sb + a_sp[i], Ah + a_go[i] + p * BK);
                cp_async16(sb + AL_OFF * 2 + a_sp[i], Al + a_go[i] + p * BK);
            }
#pragma unroll
            for (int i = 0; i < B_IT; i++) {
                cp_async16(sb + BH_OFF * 2 + b_sp[i], Bh + b_go[i] + p * BK);
                cp_async16(sb + (BH_OFF + BN * LDB) * 2 + b_sp[i], Bl + b_go[i] + p * BK);
            }
        }
        asm volatile("cp.async.commit_group;" ::: "memory");
    }

    for (int kt = 0; kt < T; kt++) {
        asm volatile("cp.async.wait_group %0;" :: "n"(STAGES - 2) : "memory");
        __syncthreads();
        {
            int tl = kt + STAGES - 1;
            if (tl < T) {
                uint32_t sb = sbase + (uint32_t)((tl % STAGES) * STG) * 2u;
#pragma unroll
                for (int i = 0; i < A_IT; i++) {
                    cp_async16(sb + a_sp[i], Ah + a_go[i] + tl * BK);
                    cp_async16(sb + AL_OFF * 2 + a_sp[i], Al + a_go[i] + tl * BK);
                }
#pragma unroll
                for (int i = 0; i < B_IT; i++) {
                    cp_async16(sb + BH_OFF * 2 + b_sp[i], Bh + b_go[i] + tl * BK);
                    cp_async16(sb + (BH_OFF + BN * LDB) * 2 + b_sp[i], Bl + b_go[i] + tl * BK);
                }
            }
            asm volatile("cp.async.commit_group;" ::: "memory");
        }

        const uint32_t stg = sbase + (uint32_t)((kt % STAGES) * STG) * 2u;
#pragma unroll
        for (int kk = 0; kk < BK; kk += 16) {
            uint32_t ah[MT][4], al[MT][4];
#pragma unroll
            for (int mt = 0; mt < MT; mt++) {
                uint32_t aa = stg + a_lane + (uint32_t)((wm0 + mt * 16) * LDB + kk) * 2u;
                LDSM4(ah[mt], aa);
                LDSM4(al[mt], aa + (uint32_t)(AL_OFF * 2));
            }
#pragma unroll
            for (int pr = 0; pr < NPAIR; pr++) {
                uint32_t bh4[4], bl4[4];
                uint32_t ba = stg + (uint32_t)(BH_OFF * 2) + b_lane
                            + (uint32_t)((wn0 + pr * 16) * LDB + kk) * 2u;
                LDSM4(bh4, ba);
                LDSM4(bl4, ba + (uint32_t)(BN * LDB * 2));
                const int nt0 = pr * 2, nt1 = pr * 2 + 1;
#pragma unroll
                for (int mt = 0; mt < MT; mt++) {
                    mma_bf16(acc[mt][nt0], ah[mt][0], ah[mt][1], ah[mt][2], ah[mt][3], bh4[0], bh4[1]);
                    mma_bf16(acc[mt][nt0], ah[mt][0], ah[mt][1], ah[mt][2], ah[mt][3], bl4[0], bl4[1]);
                    mma_bf16(acc[mt][nt0], al[mt][0], al[mt][1], al[mt][2], al[mt][3], bh4[0], bh4[1]);
                    mma_bf16(acc[mt][nt1], ah[mt][0], ah[mt][1], ah[mt][2], ah[mt][3], bh4[2], bh4[3]);
                    mma_bf16(acc[mt][nt1], ah[mt][0], ah[mt][1], ah[mt][2], ah[mt][3], bl4[2], bl4[3]);
                    mma_bf16(acc[mt][nt1], al[mt][0], al[mt][1], al[mt][2], al[mt][3], bh4[2], bh4[3]);
                }
            }
        }
    }

#pragma unroll
    for (int mt = 0; mt < MT; mt++) {
        const int r0 = m0 + wm0 + mt * 16 + g;
#pragma unroll
        for (int nt = 0; nt < 8; nt++) {
            const int cc = n0 + wn0 + nt * 8 + 2 * t;
            float v00 = acc[mt][nt][0] * alpha, v01 = acc[mt][nt][1] * alpha;
            float v10 = acc[mt][nt][2] * alpha, v11 = acc[mt][nt][3] * alpha;
            if (mode == 0) {
                float2 u0; u0.x = v00; u0.y = v01;
                float2 u1; u1.x = v10; u1.y = v11;
                *(float2*)&C[coff + (long long)r0 * ldc + cc]       = u0;
                *(float2*)&C[coff + (long long)(r0 + 8) * ldc + cc] = u1;
            } else {
                __nv_bfloat16 h0, l0, h1, l1;
                split_bf16(v00, h0, l0); split_bf16(v01, h1, l1);
                __nv_bfloat162 hp; hp.x = h0; hp.y = h1;
                __nv_bfloat162 lp; lp.x = l0; lp.y = l1;
                *(__nv_bfloat162*)&Ch[coff + (long long)r0 * ldc + cc] = hp;
                *(__nv_bfloat162*)&Cl[coff + (long long)r0 * ldc + cc] = lp;
                split_bf16(v10, h0, l0); split_bf16(v11, h1, l1);
                hp.x = h0; hp.y = h1; lp.x = l0; lp.y = l1;
                *(__nv_bfloat162*)&Ch[coff + (long long)(r0 + 8) * ldc + cc] = hp;
                *(__nv_bfloat162*)&Cl[coff + (long long)(r0 + 8) * ldc + cc] = lp;
            }
        }
    }
}

// ===========================================================================
// Narrow 3xBF16 GEMM (BN=64) — proven R4 kernel for Q/K projections.
// ===========================================================================
template<int BN>
__global__ void __launch_bounds__(256)
gemm_bf16x3(const __nv_bfloat16* __restrict__ Ah, const __nv_bfloat16* __restrict__ Al,
            const __nv_bfloat16* __restrict__ Bh, const __nv_bfloat16* __restrict__ Bl,
            __nv_bfloat16* __restrict__ Ch, __nv_bfloat16* __restrict__ Cl,
            int Kdim, int lda, int ldb, int ldc,
            long long sAo, long long sAi, long long sBo, long long sBi,
            long long sCo, long long sCi, int inner)
{
    constexpr int BM = 128, BK = 32, STAGES = 4;
    constexpr int LDB = 40;
    constexpr int AL_OFF = BM * LDB;
    constexpr int BH_OFF = 2 * BM * LDB;
    constexpr int STG    = 2 * (BM + BN) * LDB;
    constexpr int WM = 4;
    constexpr int MT = (BM / WM) / 16;
    constexpr int NT = (BN / 2) / 8;
    constexpr int A_IT = BM * 4 / 256;
    constexpr int B_IT = BN * 4 / 256;

    extern __shared__ __nv_bfloat16 sm[];
    const int tid = threadIdx.x, wid = tid >> 5, lane = tid & 31;
    const int g = lane >> 2, t = lane & 3;

    const int z  = blockIdx.z;
    const int zo = z / inner, zi = z - zo * inner;
    Ah += zo * sAo + zi * sAi;  Al += zo * sAo + zi * sAi;
    Bh += zo * sBo + zi * sBi;  Bl += zo * sBo + zi * sBi;
    const long long coff = zo * sCo + zi * sCi;
    const int m0 = blockIdx.y * BM, n0 = blockIdx.x * BN;
    const int wm0 = (wid % WM) * (BM / WM);
    const int wn0 = (wid / WM) * (BN / 2);
    const uint32_t sbase = smem_u32(sm);

    int a_go[A_IT]; uint32_t a_sp[A_IT];
#pragma unroll
    for (int i = 0; i < A_IT; i++) {
        int c = tid + i * 256;
        int row = c >> 2, kc = (c & 3) * 8;
        a_go[i] = (m0 + row) * lda + kc;
        a_sp[i] = (uint32_t)(row * LDB + kc) * 2u;
    }
    int b_go[B_IT]; uint32_t b_sp[B_IT];
#pragma unroll
    for (int i = 0; i < B_IT; i++) {
        int c = tid + i * 256;
        int row = c >> 2, kc = (c & 3) * 8;
        b_go[i] = (n0 + row) * ldb + kc;
        b_sp[i] = (uint32_t)(row * LDB + kc) * 2u;
    }

    const int T = Kdim / BK;
    float acc[MT][NT][4];
#pragma unroll
    for (int i = 0; i < MT; i++)
#pragma unroll
        for (int j = 0; j < NT; j++)
#pragma unroll
            for (int r = 0; r < 4; r++) acc[i][j][r] = 0.f;

#pragma unroll
    for (int p = 0; p < STAGES - 1; p++) {
        if (p < T) {
            uint32_t sb = sbase + (uint32_t)((p % STAGES) * STG) * 2u;
#pragma unroll
            for (int i = 0; i < A_IT; i++) {
                cp_async16(sb + a_sp[i], Ah + a_go[i] + p * BK);
                cp_async16(sb + AL_OFF * 2 + a_sp[i], Al + a_go[i] + p * BK);
            }
#pragma unroll
            for (int i = 0; i < B_IT; i++) {
                cp_async16(sb + BH_OFF * 2 + b_sp[i], Bh + b_go[i] + p * BK);
                cp_async16(sb + (BH_OFF + BN * LDB) * 2 + b_sp[i], Bl + b_go[i] + p * BK);
            }
        }
        asm volatile("cp.async.commit_group;" ::: "memory");
    }

    for (int kt = 0; kt < T; kt++) {
        asm volatile("cp.async.wait_group %0;" :: "n"(STAGES - 2) : "memory");
        __syncthreads();
        {
            int tl = kt + STAGES - 1;
            if (tl < T) {
                uint32_t sb = sbase + (uint32_t)((tl % STAGES) * STG) * 2u;
#pragma unroll
                for (int i = 0; i < A_IT; i++) {
                    cp_async16(sb + a_sp[i], Ah + a_go[i] + tl * BK);
                    cp_async16(sb + AL_OFF * 2 + a_sp[i], Al + a_go[i] + tl * BK);
                }
#pragma unroll
                for (int i = 0; i < B_IT; i++) {
                    cp_async16(sb + BH_OFF * 2 + b_sp[i], Bh + b_go[i] + tl * BK);
                    cp_async16(sb + (BH_OFF + BN * LDB) * 2 + b_sp[i], Bl + b_go[i] + tl * BK);
                }
            }
            asm volatile("cp.async.commit_group;" ::: "memory");
        }

        const __nv_bfloat16* st = sm + (kt % STAGES) * STG;
        const __nv_bfloat16* sB = st + BH_OFF;
#pragma unroll
        for (int kk = 0; kk < BK; kk += 16) {
            uint32_t bh[NT][2], bl[NT][2];
#pragma unroll
            for (int nt = 0; nt < NT; nt++) {
                const __nv_bfloat16* bp = sB + (wn0 + nt * 8 + g) * LDB + kk + 2 * t;
                bh[nt][0] = lds_u32(bp);
                bh[nt][1] = lds_u32(bp + 8);
                bl[nt][0] = lds_u32(bp + BN * LDB);
                bl[nt][1] = lds_u32(bp + BN * LDB + 8);
            }
#pragma unroll
            for (int mt = 0; mt < MT; mt++) {
                const __nv_bfloat16* ap = st + (wm0 + mt * 16 + g) * LDB + kk + 2 * t;
                uint32_t ah0 = lds_u32(ap);
                uint32_t ah1 = lds_u32(ap + 8 * LDB);
                uint32_t ah2 = lds_u32(ap + 8);
                uint32_t ah3 = lds_u32(ap + 8 * LDB + 8);
                const __nv_bfloat16* alp = ap + AL_OFF;
                uint32_t al0 = lds_u32(alp);
                uint32_t al1 = lds_u32(alp + 8 * LDB);
                uint32_t al2 = lds_u32(alp + 8);
                uint32_t al3 = lds_u32(alp + 8 * LDB + 8);
#pragma unroll
                for (int nt = 0; nt < NT; nt++) {
                    mma_bf16(acc[mt][nt], ah0, ah1, ah2, ah3, bh[nt][0], bh[nt][1]);
                    mma_bf16(acc[mt][nt], ah0, ah1, ah2, ah3, bl[nt][0], bl[nt][1]);
                    mma_bf16(acc[mt][nt], al0, al1, al2, al3, bh[nt][0], bh[nt][1]);
                }
            }
        }
    }

#pragma unroll
    for (int mt = 0; mt < MT; mt++) {
        const int r0 = m0 + wm0 + mt * 16 + g;
#pragma unroll
        for (int nt = 0; nt < NT; nt++) {
            const int cc = n0 + wn0 + nt * 8 + 2 * t;
            __nv_bfloat16 h0, l0, h1, l1;
            split_bf16(acc[mt][nt][0], h0, l0); split_bf16(acc[mt][nt][1], h1, l1);
            __nv_bfloat162 hp; hp.x = h0; hp.y = h1;
            __nv_bfloat162 lp; lp.x = l0; lp.y = l1;
            *(__nv_bfloat162*)&Ch[coff + (long long)r0 * ldc + cc] = hp;
            *(__nv_bfloat162*)&Cl[coff + (long long)r0 * ldc + cc] = lp;
            split_bf16(acc[mt][nt][2], h0, l0); split_bf16(acc[mt][nt][3], h1, l1);
            hp.x = h0; hp.y = h1; lp.x = l0; lp.y = l1;
            *(__nv_bfloat162*)&Ch[coff + (long long)(r0 + 8) * ldc + cc] = hp;
            *(__nv_bfloat162*)&Cl[coff + (long long)(r0 + 8) * ldc + cc] = lp;
        }
    }
}

// ---------------- elementwise kernels ----------------
__global__ void split_copy_kernel(const float4* __restrict__ in,
                                  __nv_bfloat16* __restrict__ oh,
                                  __nv_bfloat16* __restrict__ ol, int n4)
{
    int i = blockIdx.x * blockDim.x + threadIdx.x;
    if (i < n4) {
        float4 v = in[i];
        __nv_bfloat16 h, l;
        __nv_bfloat162 h01, h23, l01, l23;
        split_bf16(v.x, h, l); h01.x = h; l01.x = l;
        split_bf16(v.y, h, l); h01.y = h; l01.y = l;
        split_bf16(v.z, h, l); h23.x = h; l23.x = l;
        split_bf16(v.w, h, l); h23.y = h; l23.y = l;
        ((__nv_bfloat162*)oh)[2 * i] = h01; ((__nv_bfloat162*)oh)[2 * i + 1] = h23;
        ((__nv_bfloat162*)ol)[2 * i] = l01; ((__nv_bfloat162*)ol)[2 * i + 1] = l23;
    }
}

__global__ void transpose_split_kernel(const float* __restrict__ in,
                                       __nv_bfloat16* __restrict__ oh,
                                       __nv_bfloat16* __restrict__ ol,
                                       int ldi, int ldo,
                                       long long sIo, long long sIi,
                                       long long sOo, long long sOi, int inner)
{
    __shared__ float tile[32][33];
    const int z  = blockIdx.z;
    const int zo = z / inner, zi = z - zo * inner;
    const float* ip = in + zo * sIo + zi * sIi;
    const long long oo = zo * sOo + zi * sOi;
    const int c0 = blockIdx.x * 32, r0 = blockIdx.y * 32;
    const int tx = threadIdx.x, ty = threadIdx.y;
#pragma unroll
    for (int i = 0; i < 32; i += 8)
        tile[ty + i][tx] = ip[(long long)(r0 + ty + i) * ldi + c0 + tx];
    __syncthreads();
#pragma unroll
    for (int i = 0; i < 32; i += 8) {
        __nv_bfloat16 h, l;
        split_bf16(tile[tx][ty + i], h, l);
        long long o = oo + (long long)(c0 + ty + i) * ldo + r0 + tx;
        oh[o] = h; ol[o] = l;
    }
}

// 32x32 tile transpose -> 2-plane int8, scale per OUTPUT row (scale[zo*1024+row])
__global__ void quant_transpose_kernel(const float* __restrict__ in,
                                       int8_t* __restrict__ p1, int8_t* __restrict__ p0,
                                       const float* __restrict__ scale,
                                       int ldi, int ldo,
                                       long long sIo, long long sIi,
                                       long long sOo, long long sOi, int inner)
{
    __shared__ float tile[32][33];
    const int z  = blockIdx.z;
    const int zo = z / inner, zi = z - zo * inner;
    const float* ip = in + zo * sIo + zi * sIi;
    const long long oo = zo * sOo + zi * sOi;
    const int c0 = blockIdx.x * 32, r0 = blockIdx.y * 32;
    const int tx = threadIdx.x, ty = threadIdx.y;
#pragma unroll
    for (int i = 0; i < 32; i += 8)
        tile[ty + i][tx] = ip[(long long)(r0 + ty + i) * ldi + c0 + tx];
    __syncthreads();
#pragma unroll
    for (int i = 0; i < 32; i += 8) {
        const int orow = c0 + ty + i;
        const float inv = 1.0f / scale[zo * 1024 + orow];
        int8_t q1, q0;
        quant2(tile[tx][ty + i], inv, q1, q0);
        long long o = oo + (long long)orow * ldo + r0 + tx;
        p1[o] = q1; p0[o] = q0;
    }
}

// per-row absmax/16256 over contiguous rows of width K. one block per row.
__global__ void rowmax_kernel(const float* __restrict__ in, float* __restrict__ s, int K)
{
    __shared__ float red[8];
    const long long row = (long long)blockIdx.x * K;
    const int tid = threadIdx.x, lane = tid & 31, warp = tid >> 5;
    float m = 0.f;
    for (int i = tid; i < K / 4; i += 256) {
        float4 v = ((const float4*)(in + row))[i];
        m = fmaxf(m, fmaxf(fmaxf(fabsf(v.x), fabsf(v.y)), fmaxf(fabsf(v.z), fabsf(v.w))));
    }
#pragma unroll
    for (int o = 16; o; o >>= 1) m = fmaxf(m, __shfl_xor_sync(0xffffffffu, m, o));
    if (lane == 0) red[warp] = m;
    __syncthreads();
    if (tid == 0) {
#pragma unroll
        for (int j = 1; j < 8; j++) m = fmaxf(m, red[j]);
        s[blockIdx.x] = fmaxf(m, 1e-30f) * (1.0f / 16256.0f);
    }
}

// per-column absmax/16256 over R rows of width 1024, per z.
__global__ void colmax_kernel(const float* __restrict__ in, float* __restrict__ s, int R)
{
    const int z = blockIdx.y;
    const int c = blockIdx.x * 256 + threadIdx.x;
    const float* ip = in + (long long)z * R * 1024 + c;
    float m = 0.f;
    for (int r = 0; r < R; r++) m = fmaxf(m, fabsf(ip[(long long)r * 1024]));
    s[z * 1024 + c] = fmaxf(m, 1e-30f) * (1.0f / 16256.0f);
}

// quantize contiguous rows into 2 int8 planes (row = i4/(K/4)).
__global__ void rowquant_kernel(const float4* __restrict__ in,
                                int8_t* __restrict__ p1, int8_t* __restrict__ p0,
                                const float* __restrict__ s, int K4, long long n4)
{
    long long i = (long long)blockIdx.x * blockDim.x + threadIdx.x;
    if (i < n4) {
        const float inv = 1.0f / s[i / K4];
        float4 v = in[i];
        char4 q1, q0;
        quant2(v.x, inv, (int8_t&)q1.x, (int8_t&)q0.x);
        quant2(v.y, inv, (int8_t&)q1.y, (int8_t&)q0.y);
        quant2(v.z, inv, (int8_t&)q1.z, (int8_t&)q0.z);
        quant2(v.w, inv, (int8_t&)q1.w, (int8_t&)q0.w);
        ((char4*)p1)[i] = q1; ((char4*)p0)[i] = q0;
    }
}

// softmax rows (fp32 in, bf16 hi/lo out), one block per 1024-wide row
__global__ void softmax_split_kernel(const float* __restrict__ Sf,
                                     __nv_bfloat16* __restrict__ Sh,
                                     __nv_bfloat16* __restrict__ Sl)
{
    __shared__ float red[8];
    const long long row = (long long)blockIdx.x * N_;
    const float4* p = (const float4*)(Sf + row);
    const int tid = threadIdx.x, lane = tid & 31, warp = tid >> 5;
    float4 x = p[tid];
    float m = fmaxf(fmaxf(x.x, x.y), fmaxf(x.z, x.w));
#pragma unroll
    for (int o = 16; o; o >>= 1) m = fmaxf(m, __shfl_xor_sync(0xffffffffu, m, o));
    if (lane == 0) red[warp] = m;
    __syncthreads();
    m = red[0];
#pragma unroll
    for (int j = 1; j < 8; j++) m = fmaxf(m, red[j]);
    __syncthreads();
    x.x = __expf(x.x - m); x.y = __expf(x.y - m);
    x.z = __expf(x.z - m); x.w = __expf(x.w - m);
    float s = x.x + x.y + x.z + x.w;
#pragma unroll
    for (int o = 16; o; o >>= 1) s += __shfl_xor_sync(0xffffffffu, s, o);
    if (lane == 0) red[warp] = s;
    __syncthreads();
    s = red[0];
#pragma unroll
    for (int j = 1; j < 8; j++) s += red[j];
    const float inv = 1.0f / s;
    __nv_bfloat16 h, l;
    __nv_bfloat162 h01, h23, l01, l23;
    split_bf16(x.x * inv, h, l); h01.x = h; l01.x = l;
    split_bf16(x.y * inv, h, l); h01.y = h; l01.y = l;
    split_bf16(x.z * inv, h, l); h23.x = h; l23.x = l;
    split_bf16(x.w * inv, h, l); h23.y = h; l23.y = l;
    ((__nv_bfloat162*)(Sh + row))[2 * tid]     = h01;
    ((__nv_bfloat162*)(Sh + row))[2 * tid + 1] = h23;
    ((__nv_bfloat162*)(Sl + row))[2 * tid]     = l01;
    ((__nv_bfloat162*)(Sl + row))[2 * tid + 1] = l23;
}

// ---------------- launch ----------------
extern "C" void kernel_launch(void* const* d_in, const int* in_sizes, int n_in,
                              void* d_out, int out_size)
{
    (void)in_sizes; (void)n_in; (void)out_size;
    const float* query = (const float*)d_in[0];
    const float* key   = (const float*)d_in[1];
    const float* value = (const float*)d_in[2];
    const float* w_q   = (const float*)d_in[3];
    const float* w_k   = (const float*)d_in[4];
    const float* w_v   = (const float*)d_in[5];
    const float* w_o   = (const float*)d_in[6];
    float*       out   = (float*)d_out;

    __nv_bfloat16 *qh, *ql, *kh, *kl, *wqTh, *wqTl, *wkTh, *wkTl;
    __nv_bfloat16 *Qh, *Ql, *Kh, *Kl, *Sh, *Sl, *Vth, *Vtl;
    float *Sf, *Of, *sv, *swv, *swo, *sp;
    int8_t *v1, *v0, *wv1, *wv0, *wo1, *wo0, *P1, *P0;
    cudaGetSymbolAddress((void**)&qh, g_qh);   cudaGetSymbolAddress((void**)&ql, g_ql);
    cudaGetSymbolAddress((void**)&kh, g_kh);   cudaGetSymbolAddress((void**)&kl, g_kl);
    cudaGetSymbolAddress((void**)&wqTh, g_wqTh); cudaGetSymbolAddress((void**)&wqTl, g_wqTl);
    cudaGetSymbolAddress((void**)&wkTh, g_wkTh); cudaGetSymbolAddress((void**)&wkTl, g_wkTl);
    cudaGetSymbolAddress((void**)&Qh, g_Qh);   cudaGetSymbolAddress((void**)&Ql, g_Ql);
    cudaGetSymbolAddress((void**)&Kh, g_Kh);   cudaGetSymbolAddress((void**)&Kl, g_Kl);
    cudaGetSymbolAddress((void**)&Sf, g_Sf);
    cudaGetSymbolAddress((void**)&Sh, g_Sh);   cudaGetSymbolAddress((void**)&Sl, g_Sl);
    cudaGetSymbolAddress((void**)&Vth, g_Vth); cudaGetSymbolAddress((void**)&Vtl, g_Vtl);
    cudaGetSymbolAddress((void**)&Of, g_Of);
    cudaGetSymbolAddress((void**)&v1, g_v1);   cudaGetSymbolAddress((void**)&v0, g_v0);
    cudaGetSymbolAddress((void**)&sv, g_sv);
    cudaGetSymbolAddress((void**)&wv1, g_wv1); cudaGetSymbolAddress((void**)&wv0, g_wv0);
    cudaGetSymbolAddress((void**)&swv, g_swv);
    cudaGetSymbolAddress((void**)&wo1, g_wo1); cudaGetSymbolAddress((void**)&wo0, g_wo0);
    cudaGetSymbolAddress((void**)&swo, g_swo);
    cudaGetSymbolAddress((void**)&P1, g_P1);   cudaGetSymbolAddress((void**)&P0, g_P0);
    cudaGetSymbolAddress((void**)&sp, g_sp);

    constexpr int SMEM_W  = 3 * 2 * (128 + 256) * 40 * 2;   // 184320
    constexpr int SMEM_64 = 4 * 2 * (128 + 64)  * 40 * 2;   // 122880
    constexpr int SMEM_I8 = 3 * (2 * 64 * 48 + 2 * 128 * 48); // 55296
    cudaFuncSetAttribute(gemm_bf16x3_wide, cudaFuncAttributeMaxDynamicSharedMemorySize, SMEM_W);
    cudaFuncSetAttribute(gemm_bf16x3<64>,  cudaFuncAttributeMaxDynamicSharedMemorySize, SMEM_64);
    cudaFuncSetAttribute(gemm_i8,          cudaFuncAttributeMaxDynamicSharedMemorySize, SMEM_I8);

    const long long MB = 1024LL * 1024LL;
    const int ZBH = B_ * H_;

    // 0-3: quantize value + w_v
    rowmax_kernel<<<B_ * N_, 256>>>(value, sv, DM_);
    rowquant_kernel<<<(B_ * N_ * DM_ / 4 + 255) / 256, 256>>>(
        (const float4*)value, v1, v0, sv, DM_ / 4, (long long)B_ * N_ * DM_ / 4);
    colmax_kernel<<<dim3(4, H_), 256>>>(w_v, swv, DM_);
    quant_transpose_kernel<<<dim3(DV_ / 32, DM_ / 32, H_), dim3(32, 8)>>>(
        w_v, wv1, wv0, swv, DV_, DM_, (long long)DM_ * DV_, 0, (long long)DV_ * DM_, 0, 1);
    // 4
    split_copy_kernel<<<(B_ * N_ * DM_ / 4 + 255) / 256, 256>>>((const float4*)query, qh, ql, B_ * N_ * DM_ / 4);
    // 5: int8 V-proj -> Vt split  (ncu -s 5 profiles this)
    gemm_i8<<<dim3(8, 16, ZBH), 256, SMEM_I8>>>(
        wv1, wv0, v1, v0, swv, sv, nullptr, Vth, Vtl,
        DM_, DM_, DM_, N_,
        0, (long long)DV_ * DM_,
        (long long)N_ * DM_, 0,
        (long long)H_ * DV_ * N_, (long long)DV_ * N_,
        0, DV_, N_, 0,
        H_, 1);
    // 6-8: remaining prep
    split_copy_kernel<<<(B_ * N_ * DM_ / 4 + 255) / 256, 256>>>((const float4*)key, kh, kl, B_ * N_ * DM_ / 4);
    transpose_split_kernel<<<dim3(DK_ / 32, DM_ / 32, H_), dim3(32, 8)>>>(
        w_q, wqTh, wqTl, DK_, DM_, (long long)DM_ * DK_, 0, (long long)DK_ * DM_, 0, 1);
    transpose_split_kernel<<<dim3(DK_ / 32, DM_ / 32, H_), dim3(32, 8)>>>(
        w_k, wkTh, wkTl, DK_, DM_, (long long)DM_ * DK_, 0, (long long)DK_ * DM_, 0, 1);
    // 9-10: Q/K projections (bf16 3x)
    gemm_bf16x3<64><<<dim3(1, 8, ZBH), 256, SMEM_64>>>(
        qh, ql, wqTh, wqTl, Qh, Ql, DM_, DM_, DM_, DK_,
        (long long)N_ * DM_, 0, 0, (long long)DK_ * DM_,
        (long long)H_ * N_ * DK_, (long long)N_ * DK_, H_);
    gemm_bf16x3<64><<<dim3(1, 8, ZBH), 256, SMEM_64>>>(
        kh, kl, wkTh, wkTl, Kh, Kl, DM_, DM_, DM_, DK_,
        (long long)N_ * DM_, 0, 0, (long long)DK_ * DM_,
        (long long)H_ * N_ * DK_, (long long)N_ * DK_, H_);
    // 11: scores (bf16 3x wide), 12: softmax
    gemm_bf16x3_wide<<<dim3(4, 8, ZBH), 512, SMEM_W>>>(
        Qh, Ql, Kh, Kl, Sf, nullptr, nullptr, DK_, DK_, DK_, N_,
        (long long)N_ * DK_, 0, (long long)N_ * DK_, 0, (long long)N_ * N_, 0,
        1, 0.125f, 0);
    softmax_split_kernel<<<ZBH * N_, 256>>>(Sf, Sh, Sl);
    // 13: S·V (bf16 3x wide) -> Of
    gemm_bf16x3_wide<<<dim3(4, 8, ZBH), 512, SMEM_W>>>(
        Sh, Sl, Vth, Vtl, Of, nullptr, nullptr, N_, N_, N_, DV_,
        (long long)N_ * N_, 0, (long long)DV_ * N_, 0, (long long)N_ * DV_, 0,
        1, 1.0f, 0);
    // 14-17: quantize O->P and w_o
    colmax_kernel<<<dim3(4, B_), 256>>>(Of, sp, H_ * N_);
    quant_transpose_kernel<<<dim3(32, 32, ZBH), dim3(32, 8)>>>(
        Of, P1, P0, sp, DV_, H_ * N_,
        (long long)H_ * MB, MB, (long long)H_ * MB, (long long)N_, H_);
    rowmax_kernel<<<DM_, 256>>>(w_o, swo, H_ * DV_);
    rowquant_kernel<<<(DM_ * H_ * DV_ / 4 + 255) / 256, 256>>>(
        (const float4*)w_o, wo1, wo0, swo, H_ * DV_ / 4, (long long)DM_ * H_ * DV_ / 4);
    // 18: int8 w_o GEMM -> out (fp32), K=16384
    gemm_i8<<<dim3(8, 16, B_), 256, SMEM_I8>>>(
        wo1, wo0, P1, P0, swo, sp, out, nullptr, nullptr,
        H_ * N_, H_ * N_, H_ * N_, DV_,
        0, 0, (long long)DV_ * H_ * N_, 0, (long long)DM_ * DV_, 0,
        0, 0, DV_, 0,
        1, 0);
}